// round 15
// baseline (speedup 1.0000x reference)
#include <cuda_runtime.h>
#include <cuda_fp16.h>
#include <math.h>
#include <stdint.h>

#define BATCH 8
#define SEQ   1024
#define DIM   1024
#define HEADS 16
#define DH    64
#define HFF   4096
#define MROWS (BATCH*SEQ)   // 8192
#define QKVN  (3*DIM)       // 3072

// ---------------- scratch (static device arrays: allocation-free) ----------
__device__ __half g_ln [(size_t)MROWS*DIM];
__device__ __half g_qkv[(size_t)MROWS*QKVN];
__device__ float  g_x1 [(size_t)MROWS*DIM];
__device__ __half g_hid[(size_t)MROWS*HFF];
__device__ float  g_b3 [QKVN];
// single fp16 weight planes: wqkv (3M) | wo (1M) | w1 (4M) | w2 (4M)
#define HOFF_QKV 0
#define HOFF_O   ((size_t)3*DIM*DIM)
#define HOFF_1   ((size_t)4*DIM*DIM)
#define HOFF_2   ((size_t)4*DIM*DIM + (size_t)HFF*DIM)
__device__ __half g_w16[(size_t)4*DIM*DIM + (size_t)2*HFF*DIM];

// ==================== helpers ====================
__device__ __forceinline__ uint32_t smem_u32(const void* p) {
    uint32_t a;
    asm("{ .reg .u64 t; cvta.to.shared.u64 t, %1; cvt.u32.u64 %0, t; }"
        : "=r"(a) : "l"(p));
    return a;
}
__device__ __forceinline__ void cp_async16(uint32_t dst, const void* src) {
    uint64_t g;
    asm("cvta.to.global.u64 %0, %1;" : "=l"(g) : "l"(src));
    asm volatile("cp.async.cg.shared.global [%0], [%1], 16;"
                 :: "r"(dst), "l"(g) : "memory");
}
#define CP_COMMIT() asm volatile("cp.async.commit_group;" ::: "memory")
#define CP_WAIT0()  asm volatile("cp.async.wait_group 0;"  ::: "memory")
#define CP_WAIT1()  asm volatile("cp.async.wait_group 1;"  ::: "memory")

__device__ __forceinline__ uint32_t pack_h2(float a, float b) {
    __half2 h = __floats2half2_rn(a, b);
    return *(uint32_t*)&h;
}

#define LDM4(r0, r1, r2, r3, addr) \
    asm volatile("ldmatrix.sync.aligned.m8n8.x4.shared.b16 {%0,%1,%2,%3}, [%4];" \
                 : "=r"(r0), "=r"(r1), "=r"(r2), "=r"(r3) : "r"(addr))
#define LDM2T(r0, r1, addr) \
    asm volatile("ldmatrix.sync.aligned.m8n8.x2.trans.shared.b16 {%0,%1}, [%2];" \
                 : "=r"(r0), "=r"(r1) : "r"(addr))
#define MMAH16816(c, a, b) \
    asm volatile("mma.sync.aligned.m16n8k16.row.col.f32.f16.f16.f32 " \
                 "{%0,%1,%2,%3}, {%4,%5,%6,%7}, {%8,%9}, {%0,%1,%2,%3};" \
                 : "+f"((c)[0]), "+f"((c)[1]), "+f"((c)[2]), "+f"((c)[3]) \
                 : "r"((a)[0]), "r"((a)[1]), "r"((a)[2]), "r"((a)[3]), \
                   "r"((b)[0]), "r"((b)[1]))

// ============ fused prep: all weight conversions + bcat + LN1 ===============
// block ranges:
//   [0, 8192)         wq|wk|wv|wo -> fp16 (4M half2 via 256 thr/blk, 2/thr)
//   [8192, 16384)     w1 -> fp16
//   [16384, 24576)    w2 -> fp16
//   [24576, 24588)    bias concat
//   [24588, 32780)    LN1 rows
#define PREP_BLOCKS 32780
__global__ __launch_bounds__(256) void prep_kernel(
    const float* __restrict__ wq, const float* __restrict__ wk,
    const float* __restrict__ wv, const float* __restrict__ wo,
    const float* __restrict__ w1, const float* __restrict__ w2,
    const float* __restrict__ bq, const float* __restrict__ bk,
    const float* __restrict__ bv,
    const float* __restrict__ x,
    const float* __restrict__ alpha, const float* __restrict__ beta,
    __half* __restrict__ w16, float* __restrict__ b3,
    __half* __restrict__ ln)
{
    const int bid = blockIdx.x, tid = threadIdx.x;
    if (bid < 8192) {                       // projection weights
        const int n2p = DIM * DIM / 2;
        const int i = bid * 256 + tid;      // [0, 4*n2p)
        const float* src = (i < n2p) ? wq : (i < 2 * n2p) ? wk
                         : (i < 3 * n2p) ? wv : wo;
        const float2 v = ((const float2*)src)[i & (n2p - 1)];
        ((__half2*)(w16 + HOFF_QKV))[i] = __floats2half2_rn(v.x, v.y);
        return;
    }
    if (bid < 16384) {
        const int i = (bid - 8192) * 256 + tid;
        const float2 v = ((const float2*)w1)[i];
        ((__half2*)(w16 + HOFF_1))[i] = __floats2half2_rn(v.x, v.y);
        return;
    }
    if (bid < 24576) {
        const int i = (bid - 16384) * 256 + tid;
        const float2 v = ((const float2*)w2)[i];
        ((__half2*)(w16 + HOFF_2))[i] = __floats2half2_rn(v.x, v.y);
        return;
    }
    if (bid < 24588) {
        const int i = (bid - 24576) * 256 + tid;
        if (i < DIM)            b3[i] = bq[i];
        else if (i < 2 * DIM)   b3[i] = bk[i - DIM];
        else if (i < 3 * DIM)   b3[i] = bv[i - 2 * DIM];
        return;
    }
    // ---- LN1 row ----
    __shared__ float sh_s[8], sh_q[8];
    const size_t row = bid - 24588;
    float4 v = ((const float4*)(x + row * DIM))[tid];
    float s = v.x + v.y + v.z + v.w;
    float q = v.x*v.x + v.y*v.y + v.z*v.z + v.w*v.w;
#pragma unroll
    for (int o = 16; o; o >>= 1) {
        s += __shfl_xor_sync(0xffffffffu, s, o);
        q += __shfl_xor_sync(0xffffffffu, q, o);
    }
    if ((tid & 31) == 0) { sh_s[tid >> 5] = s; sh_q[tid >> 5] = q; }
    __syncthreads();
    if (tid < 32) {
        s = (tid < 8) ? sh_s[tid] : 0.f;
        q = (tid < 8) ? sh_q[tid] : 0.f;
#pragma unroll
        for (int o = 4; o; o >>= 1) {
            s += __shfl_xor_sync(0xffffffffu, s, o);
            q += __shfl_xor_sync(0xffffffffu, q, o);
        }
        if (tid == 0) { sh_s[0] = s; sh_q[0] = q; }
    }
    __syncthreads();
    s = sh_s[0]; q = sh_q[0];
    const float mean = s * (1.0f / DIM);
    const float var  = (q - (float)DIM * mean * mean) * (1.0f / (DIM - 1));
    const float inv  = 1.0f / (sqrtf(fmaxf(var, 0.f)) + 1e-6f);
    const float4 a = ((const float4*)alpha)[tid];
    const float4 b = ((const float4*)beta)[tid];
    const float ox = a.x * (v.x - mean) * inv + b.x;
    const float oy = a.y * (v.y - mean) * inv + b.y;
    const float oz = a.z * (v.z - mean) * inv + b.z;
    const float ow = a.w * (v.w - mean) * inv + b.w;
    *(uint2*)((uint16_t*)ln + row * DIM + 4 * tid) =
        make_uint2(pack_h2(ox, oy), pack_h2(oz, ow));
}

// ==================== single-fp16 1-MMA GEMM, 2-stage, 3 CTAs/SM ===========
// C[m,n] = sum_k A[m,k]*B[n,k] + bias (+relu, +resid), fp32 accumulate.
// 128 threads, 2x2 warps, 64x64 warp tiles, BM=BN=128, BK=64.
template<bool OHALF>
__global__ __launch_bounds__(128, 3) void gemm_h1(
    const __half* __restrict__ A, int lda,
    const __half* __restrict__ B, int ldb,
    float* __restrict__ Cf, __half* __restrict__ Ch, int ldc,
    int K,
    const float* __restrict__ bias,
    const float* __restrict__ resid, int ldr,
    int relu)
{
    constexpr int BK = 64;
    constexpr int TBYTES = 128 * 144;
    constexpr int SS = 2 * TBYTES;        // stage = A + B (36864)

    extern __shared__ char sm[];
    const uint32_t smBase = smem_u32(sm);

    const int tid = threadIdx.x, wid = tid >> 5, lane = tid & 31;
    const int wm = wid >> 1, wn = wid & 1;
    const int m0 = blockIdx.y * 128, n0 = blockIdx.x * 128;

    float acc[4][8][4];
#pragma unroll
    for (int i = 0; i < 4; i++)
#pragma unroll
        for (int j = 0; j < 8; j++)
#pragma unroll
            for (int r = 0; r < 4; r++) acc[i][j][r] = 0.f;

    auto issue = [&](int s, int t) {
        const uint32_t sA = smBase + s * SS;
        const uint32_t sB = sA + TBYTES;
#pragma unroll
        for (int i = 0; i < 8; i++) {
            const int idx = i * 128 + tid;
            const int c = idx & 7, row = idx >> 3;
            cp_async16(sA + row * 144 + c * 16,
                       A + (size_t)(m0 + row) * lda + t * BK + c * 8);
        }
#pragma unroll
        for (int i = 0; i < 8; i++) {
            const int idx = i * 128 + tid;
            const int c = idx & 7, row = idx >> 3;
            cp_async16(sB + row * 144 + c * 16,
                       B + (size_t)(n0 + row) * ldb + t * BK + c * 8);
        }
        CP_COMMIT();
    };

    auto compute = [&](int s) {
        const uint32_t aB = smBase + s * SS;
        const uint32_t bB = aB + TBYTES;
#pragma unroll
        for (int ks = 0; ks < 4; ks++) {
            uint32_t bf[8][2];
#pragma unroll
            for (int p = 0; p < 4; p++) {
                const uint32_t rb =
                    (uint32_t)((wn * 64 + p * 16 + ((lane >> 4) & 1) * 8 + (lane & 7)) * 144
                               + ks * 32 + ((lane >> 3) & 1) * 16);
                LDM4(bf[2*p][0], bf[2*p][1], bf[2*p+1][0], bf[2*p+1][1], bB + rb);
            }
#pragma unroll
            for (int mt = 0; mt < 4; mt++) {
                uint32_t af[4];
                const uint32_t ra =
                    (uint32_t)((wm * 64 + mt * 16 + (lane & 15)) * 144
                               + ks * 32 + (lane >> 4) * 16);
                LDM4(af[0], af[1], af[2], af[3], aB + ra);
#pragma unroll
                for (int nt = 0; nt < 8; nt++) MMAH16816(acc[mt][nt], af, bf[nt]);
            }
        }
    };

    const int T = K / BK;
    issue(0, 0);
    CP_WAIT0();
    __syncthreads();

    for (int t = 0; t < T; t++) {
        const int s = t & 1;
        if (t + 1 < T) issue(s ^ 1, t + 1);
        compute(s);
        CP_WAIT0();
        __syncthreads();
    }

#pragma unroll
    for (int mt = 0; mt < 4; mt++) {
#pragma unroll
        for (int nt = 0; nt < 8; nt++) {
            const int r0 = m0 + wm * 64 + mt * 16 + (lane >> 2);
            const int cc = n0 + wn * 64 + nt * 8 + (lane & 3) * 2;
#pragma unroll
            for (int h = 0; h < 2; h++) {
                const int m = r0 + h * 8;
                float vx = acc[mt][nt][2 * h];
                float vy = acc[mt][nt][2 * h + 1];
                if (bias)  { vx += bias[cc]; vy += bias[cc + 1]; }
                if (relu)  { vx = fmaxf(vx, 0.f); vy = fmaxf(vy, 0.f); }
                if (resid) {
                    const float2 rr = *(const float2*)(resid + (size_t)m * ldr + cc);
                    vx += rr.x; vy += rr.y;
                }
                if constexpr (OHALF) {
                    *(uint32_t*)(Ch + (size_t)m * ldc + cc) = pack_h2(vx, vy);
                } else {
                    *(float2*)(Cf + (size_t)m * ldc + cc) = make_float2(vx, vy);
                }
            }
        }
    }
}

// ============== fused flash attention, double-buffered KV ===================
#define FQ_B 9216       // 64 rows * 144B
#define FKV_B 36864     // K(18432) + V(18432) one stage
#define FSMEM (FQ_B + 2*FKV_B)   // 82944

__global__ __launch_bounds__(128, 2) void flash_attn(
    const __half* __restrict__ qkv, __half* __restrict__ o)
{
    extern __shared__ char sm[];
    const uint32_t smBase = smem_u32(sm);
    const int tid = threadIdx.x, lane = tid & 31, w = tid >> 5;
    const int b = blockIdx.y >> 4, h = blockIdx.y & 15;
    const size_t rowQ  = (size_t)b * SEQ + blockIdx.x * 64;
    const size_t rowKV = (size_t)b * SEQ;
    const int colh = h * DH;

    const uint32_t sQ = smBase;
    const uint32_t sKV0 = smBase + FQ_B;

    auto loadKV = [&](int kt, int s) {
        const uint32_t sK = sKV0 + s * FKV_B;
        const size_t base = (rowKV + kt * 128) * QKVN + colh;
#pragma unroll
        for (int i = 0; i < 16; i++) {
            const int idx = i * 128 + tid;
            const int kv = idx >> 10, c = idx & 7, row = (idx >> 3) & 127;
            const size_t off = base + (size_t)row * QKVN + c * 8 + (kv + 1) * DIM;
            cp_async16(sK + kv * 18432 + row * 144 + c * 16, qkv + off);
        }
        CP_COMMIT();
    };

#pragma unroll
    for (int i = 0; i < 4; i++) {
        const int idx = i * 128 + tid;
        const int c = idx & 7, row = idx >> 3;
        cp_async16(sQ + row * 144 + c * 16,
                   qkv + (rowQ + row) * QKVN + colh + c * 8);
    }
    loadKV(0, 0);          // commits Q + KV0 together
    loadKV(1, 1);
    CP_WAIT1();            // Q + KV0 ready
    __syncthreads();

    float oacc[8][4];
#pragma unroll
    for (int i = 0; i < 8; i++)
#pragma unroll
        for (int j = 0; j < 4; j++) oacc[i][j] = 0.f;
    float m0 = -INFINITY, m1 = -INFINITY, l0 = 0.f, l1 = 0.f;

    for (int kt = 0; kt < 8; kt++) {
        const int s = kt & 1;
        const uint32_t sK = sKV0 + s * FKV_B;
        const uint32_t sV = sK + 18432;

        float sfr[16][4];
#pragma unroll
        for (int i = 0; i < 16; i++)
#pragma unroll
            for (int j = 0; j < 4; j++) sfr[i][j] = 0.f;
#pragma unroll
        for (int ks = 0; ks < 4; ks++) {
            uint32_t qa[4];
            const uint32_t ra = sQ + (w * 16 + (lane & 15)) * 144
                              + ks * 32 + (lane >> 4) * 16;
            LDM4(qa[0], qa[1], qa[2], qa[3], ra);
#pragma unroll
            for (int p = 0; p < 8; p++) {
                uint32_t kb[4];
                const uint32_t rb = sK + (p * 16 + ((lane >> 4) & 1) * 8 + (lane & 7)) * 144
                                  + ks * 32 + ((lane >> 3) & 1) * 16;
                LDM4(kb[0], kb[1], kb[2], kb[3], rb);
                MMAH16816(sfr[2*p],   qa, (&kb[0]));
                MMAH16816(sfr[2*p+1], qa, (&kb[2]));
            }
        }
        float mx0 = -INFINITY, mx1 = -INFINITY;
#pragma unroll
        for (int nt = 0; nt < 16; nt++) {
            mx0 = fmaxf(mx0, fmaxf(sfr[nt][0], sfr[nt][1]));
            mx1 = fmaxf(mx1, fmaxf(sfr[nt][2], sfr[nt][3]));
        }
        mx0 = fmaxf(mx0, __shfl_xor_sync(0xffffffffu, mx0, 1));
        mx0 = fmaxf(mx0, __shfl_xor_sync(0xffffffffu, mx0, 2));
        mx1 = fmaxf(mx1, __shfl_xor_sync(0xffffffffu, mx1, 1));
        mx1 = fmaxf(mx1, __shfl_xor_sync(0xffffffffu, mx1, 2));
        const float mn0 = fmaxf(m0, 0.125f * mx0);
        const float mn1 = fmaxf(m1, 0.125f * mx1);
        const float f0 = __expf(m0 - mn0);
        const float f1 = __expf(m1 - mn1);
        float rs0 = 0.f, rs1 = 0.f;
#pragma unroll
        for (int nt = 0; nt < 16; nt++) {
            const float p0 = __expf(fmaf(sfr[nt][0], 0.125f, -mn0));
            const float p1 = __expf(fmaf(sfr[nt][1], 0.125f, -mn0));
            const float p2 = __expf(fmaf(sfr[nt][2], 0.125f, -mn1));
            const float p3 = __expf(fmaf(sfr[nt][3], 0.125f, -mn1));
            rs0 += p0 + p1; rs1 += p2 + p3;
            sfr[nt][0] = p0; sfr[nt][1] = p1; sfr[nt][2] = p2; sfr[nt][3] = p3;
        }
        rs0 += __shfl_xor_sync(0xffffffffu, rs0, 1);
        rs0 += __shfl_xor_sync(0xffffffffu, rs0, 2);
        rs1 += __shfl_xor_sync(0xffffffffu, rs1, 1);
        rs1 += __shfl_xor_sync(0xffffffffu, rs1, 2);
        l0 = l0 * f0 + rs0; l1 = l1 * f1 + rs1;
        m0 = mn0; m1 = mn1;
#pragma unroll
        for (int dt = 0; dt < 8; dt++) {
            oacc[dt][0] *= f0; oacc[dt][1] *= f0;
            oacc[dt][2] *= f1; oacc[dt][3] *= f1;
        }
#pragma unroll
        for (int ks = 0; ks < 8; ks++) {
            uint32_t pa[4];
            pa[0] = pack_h2(sfr[2 * ks][0],     sfr[2 * ks][1]);
            pa[1] = pack_h2(sfr[2 * ks][2],     sfr[2 * ks][3]);
            pa[2] = pack_h2(sfr[2 * ks + 1][0], sfr[2 * ks + 1][1]);
            pa[3] = pack_h2(sfr[2 * ks + 1][2], sfr[2 * ks + 1][3]);
#pragma unroll
            for (int dt = 0; dt < 8; dt++) {
                uint32_t vb[2];
                const uint32_t rv = sV + (ks * 16 + (lane & 15)) * 144 + dt * 16;
                LDM2T(vb[0], vb[1], rv);
                MMAH16816(oacc[dt], pa, vb);
            }
        }
        if (kt + 1 < 8) {
            __syncthreads();
            if (kt + 2 < 8) {
                loadKV(kt + 2, s);
                CP_WAIT1();
            } else {
                CP_WAIT0();
            }
            __syncthreads();
        }
    }

    const float i0 = 1.f / l0, i1 = 1.f / l1;
    const int r = w * 16 + (lane >> 2);
    const int cc = (lane & 3) * 2;
#pragma unroll
    for (int dt = 0; dt < 8; dt++) {
        const size_t o0 = (rowQ + r) * DIM + colh + dt * 8 + cc;
        *(uint32_t*)(o + o0) = pack_h2(oacc[dt][0] * i0, oacc[dt][1] * i0);
        const size_t o1 = o0 + 8 * DIM;
        *(uint32_t*)(o + o1) = pack_h2(oacc[dt][2] * i1, oacc[dt][3] * i1);
    }
}

// ---------------- LayerNorm -> single fp16 plane (LN2) ---------------------
__global__ __launch_bounds__(256) void ln_kernel(const float* __restrict__ x,
                                                 __half* __restrict__ y,
                                                 const float* __restrict__ alpha,
                                                 const float* __restrict__ beta) {
    __shared__ float sh_s[8], sh_q[8];
    const size_t row = blockIdx.x;
    const float4* xr = (const float4*)(x + row * DIM);
    const int tid = threadIdx.x;
    float4 v = xr[tid];
    float s = v.x + v.y + v.z + v.w;
    float q = v.x*v.x + v.y*v.y + v.z*v.z + v.w*v.w;
#pragma unroll
    for (int o = 16; o; o >>= 1) {
        s += __shfl_xor_sync(0xffffffffu, s, o);
        q += __shfl_xor_sync(0xffffffffu, q, o);
    }
    if ((tid & 31) == 0) { sh_s[tid >> 5] = s; sh_q[tid >> 5] = q; }
    __syncthreads();
    if (tid < 32) {
        s = (tid < 8) ? sh_s[tid] : 0.f;
        q = (tid < 8) ? sh_q[tid] : 0.f;
#pragma unroll
        for (int o = 4; o; o >>= 1) {
            s += __shfl_xor_sync(0xffffffffu, s, o);
            q += __shfl_xor_sync(0xffffffffu, q, o);
        }
        if (tid == 0) { sh_s[0] = s; sh_q[0] = q; }
    }
    __syncthreads();
    s = sh_s[0]; q = sh_q[0];
    const float mean = s * (1.0f / DIM);
    const float var  = (q - (float)DIM * mean * mean) * (1.0f / (DIM - 1));
    const float inv  = 1.0f / (sqrtf(fmaxf(var, 0.f)) + 1e-6f);
    const float4 a = ((const float4*)alpha)[tid];
    const float4 b = ((const float4*)beta)[tid];
    const float ox = a.x * (v.x - mean) * inv + b.x;
    const float oy = a.y * (v.y - mean) * inv + b.y;
    const float oz = a.z * (v.z - mean) * inv + b.z;
    const float ow = a.w * (v.w - mean) * inv + b.w;
    *(uint2*)((uint16_t*)y + row * DIM + 4 * tid) =
        make_uint2(pack_h2(ox, oy), pack_h2(oz, ow));
}

// ---------------- launch ----------------------------------------------------
template<typename T>
static T* symaddr(const void* s) {
    void* p = nullptr;
    cudaGetSymbolAddress(&p, s);
    return (T*)p;
}

#define SMEM_H1 (2 * (2 * 128 * 144))   // 73728

extern "C" void kernel_launch(void* const* d_in, const int* in_sizes, int n_in,
                              void* d_out, int out_size) {
    (void)in_sizes; (void)n_in; (void)out_size;
    const float* x     = (const float*)d_in[0];
    const float* wq    = (const float*)d_in[2];
    const float* bq    = (const float*)d_in[3];
    const float* wk    = (const float*)d_in[4];
    const float* bk    = (const float*)d_in[5];
    const float* wv    = (const float*)d_in[6];
    const float* bv    = (const float*)d_in[7];
    const float* wo    = (const float*)d_in[8];
    const float* bo    = (const float*)d_in[9];
    const float* w1    = (const float*)d_in[10];
    const float* b1    = (const float*)d_in[11];
    const float* w2    = (const float*)d_in[12];
    const float* b2    = (const float*)d_in[13];
    const float* alpha = (const float*)d_in[14];
    const float* beta  = (const float*)d_in[15];
    float* out = (float*)d_out;

    cudaFuncSetAttribute(gemm_h1<true>,
                         cudaFuncAttributeMaxDynamicSharedMemorySize, SMEM_H1);
    cudaFuncSetAttribute(gemm_h1<false>,
                         cudaFuncAttributeMaxDynamicSharedMemorySize, SMEM_H1);
    cudaFuncSetAttribute(flash_attn,
                         cudaFuncAttributeMaxDynamicSharedMemorySize, FSMEM);

    __half* ln   = symaddr<__half>(g_ln);
    __half* qkv  = symaddr<__half>(g_qkv);
    float*  x1   = symaddr<float>(g_x1);
    __half* w16  = symaddr<__half>(g_w16);
    __half* hid  = symaddr<__half>(g_hid);
    float*  b3   = symaddr<float>(g_b3);

    // 0) fused prep: all weight conversions + bias concat + LN1
    prep_kernel<<<PREP_BLOCKS, 256>>>(wq, wk, wv, wo, w1, w2,
                                      bq, bk, bv, x, alpha, beta,
                                      w16, b3, ln);

    // 1) fused QKV projection [8192, 3072]
    dim3 gqkv(QKVN / 128, MROWS / 128, 1);
    gemm_h1<true><<<gqkv, 128, SMEM_H1>>>(
        ln, DIM, w16 + HOFF_QKV, DIM,
        nullptr, qkv, QKVN, DIM, b3, nullptr, 0, 0);

    // 2) fused attention -> fp16 plane (reuse ln buffer)
    dim3 gfa(SEQ / 64, BATCH * HEADS, 1);
    flash_attn<<<gfa, 128, FSMEM>>>(qkv, ln);

    // 3) O projection + residual x -> x1 (fp32)
    dim3 gw(DIM / 128, MROWS / 128, 1);
    gemm_h1<false><<<gw, 128, SMEM_H1>>>(
        ln, DIM, w16 + HOFF_O, DIM,
        x1, nullptr, DIM, DIM, bo, x, DIM, 0);

    // 4) LN2
    ln_kernel<<<MROWS, 256>>>(x1, ln, alpha, beta);

    // 5) FFN1 (+ReLU) -> fp16 hidden
    dim3 gf1(HFF / 128, MROWS / 128, 1);
    gemm_h1<true><<<gf1, 128, SMEM_H1>>>(
        ln, DIM, w16 + HOFF_1, DIM,
        nullptr, hid, HFF, DIM, b1, nullptr, 0, 1);

    // 6) FFN2 + residual x1 -> out (fp32)
    dim3 gf2(DIM / 128, MROWS / 128, 1);
    gemm_h1<false><<<gf2, 128, SMEM_H1>>>(
        hid, HFF, w16 + HOFF_2, HFF,
        out, nullptr, DIM, HFF, b2, x1, DIM, 0);
}

// round 16
// speedup vs baseline: 1.0461x; 1.0461x over previous
#include <cuda_runtime.h>
#include <cuda_fp16.h>
#include <math.h>
#include <stdint.h>

#define BATCH 8
#define SEQ   1024
#define DIM   1024
#define HEADS 16
#define DH    64
#define HFF   4096
#define MROWS (BATCH*SEQ)   // 8192
#define QKVN  (3*DIM)       // 3072

// ---------------- scratch (static device arrays: allocation-free) ----------
__device__ __half g_ln [(size_t)MROWS*DIM];
__device__ __half g_qkv[(size_t)MROWS*QKVN];
__device__ float  g_x1 [(size_t)MROWS*DIM];
__device__ __half g_hid[(size_t)MROWS*HFF];
__device__ float  g_b3 [QKVN];
// single fp16 weight planes: wqkv (3M) | wo (1M) | w1 (4M) | w2 (4M)
#define HOFF_QKV 0
#define HOFF_O   ((size_t)3*DIM*DIM)
#define HOFF_1   ((size_t)4*DIM*DIM)
#define HOFF_2   ((size_t)4*DIM*DIM + (size_t)HFF*DIM)
__device__ __half g_w16[(size_t)4*DIM*DIM + (size_t)2*HFF*DIM];

// ==================== helpers ====================
__device__ __forceinline__ uint32_t smem_u32(const void* p) {
    uint32_t a;
    asm("{ .reg .u64 t; cvta.to.shared.u64 t, %1; cvt.u32.u64 %0, t; }"
        : "=r"(a) : "l"(p));
    return a;
}
__device__ __forceinline__ void cp_async16(uint32_t dst, const void* src) {
    uint64_t g;
    asm("cvta.to.global.u64 %0, %1;" : "=l"(g) : "l"(src));
    asm volatile("cp.async.cg.shared.global [%0], [%1], 16;"
                 :: "r"(dst), "l"(g) : "memory");
}
#define CP_COMMIT() asm volatile("cp.async.commit_group;" ::: "memory")
#define CP_WAIT0()  asm volatile("cp.async.wait_group 0;"  ::: "memory")
#define CP_WAIT1()  asm volatile("cp.async.wait_group 1;"  ::: "memory")

__device__ __forceinline__ uint32_t pack_h2(float a, float b) {
    __half2 h = __floats2half2_rn(a, b);
    return *(uint32_t*)&h;
}

#define LDM4(r0, r1, r2, r3, addr) \
    asm volatile("ldmatrix.sync.aligned.m8n8.x4.shared.b16 {%0,%1,%2,%3}, [%4];" \
                 : "=r"(r0), "=r"(r1), "=r"(r2), "=r"(r3) : "r"(addr))
#define LDM2T(r0, r1, addr) \
    asm volatile("ldmatrix.sync.aligned.m8n8.x2.trans.shared.b16 {%0,%1}, [%2];" \
                 : "=r"(r0), "=r"(r1) : "r"(addr))
#define MMAH16816(c, a, b) \
    asm volatile("mma.sync.aligned.m16n8k16.row.col.f32.f16.f16.f32 " \
                 "{%0,%1,%2,%3}, {%4,%5,%6,%7}, {%8,%9}, {%0,%1,%2,%3};" \
                 : "+f"((c)[0]), "+f"((c)[1]), "+f"((c)[2]), "+f"((c)[3]) \
                 : "r"((a)[0]), "r"((a)[1]), "r"((a)[2]), "r"((a)[3]), \
                   "r"((b)[0]), "r"((b)[1]))

// ============ fused prep: all weight conversions + bcat + LN1 ===============
#define PREP_BLOCKS 32780
__global__ __launch_bounds__(256) void prep_kernel(
    const float* __restrict__ wq, const float* __restrict__ wk,
    const float* __restrict__ wv, const float* __restrict__ wo,
    const float* __restrict__ w1, const float* __restrict__ w2,
    const float* __restrict__ bq, const float* __restrict__ bk,
    const float* __restrict__ bv,
    const float* __restrict__ x,
    const float* __restrict__ alpha, const float* __restrict__ beta,
    __half* __restrict__ w16, float* __restrict__ b3,
    __half* __restrict__ ln)
{
    const int bid = blockIdx.x, tid = threadIdx.x;
    if (bid < 8192) {                       // projection weights
        const int n2p = DIM * DIM / 2;
        const int i = bid * 256 + tid;
        const float* src = (i < n2p) ? wq : (i < 2 * n2p) ? wk
                         : (i < 3 * n2p) ? wv : wo;
        const float2 v = ((const float2*)src)[i & (n2p - 1)];
        ((__half2*)(w16 + HOFF_QKV))[i] = __floats2half2_rn(v.x, v.y);
        return;
    }
    if (bid < 16384) {
        const int i = (bid - 8192) * 256 + tid;
        const float2 v = ((const float2*)w1)[i];
        ((__half2*)(w16 + HOFF_1))[i] = __floats2half2_rn(v.x, v.y);
        return;
    }
    if (bid < 24576) {
        const int i = (bid - 16384) * 256 + tid;
        const float2 v = ((const float2*)w2)[i];
        ((__half2*)(w16 + HOFF_2))[i] = __floats2half2_rn(v.x, v.y);
        return;
    }
    if (bid < 24588) {
        const int i = (bid - 24576) * 256 + tid;
        if (i < DIM)            b3[i] = bq[i];
        else if (i < 2 * DIM)   b3[i] = bk[i - DIM];
        else if (i < 3 * DIM)   b3[i] = bv[i - 2 * DIM];
        return;
    }
    // ---- LN1 row ----
    __shared__ float sh_s[8], sh_q[8];
    const size_t row = bid - 24588;
    float4 v = ((const float4*)(x + row * DIM))[tid];
    float s = v.x + v.y + v.z + v.w;
    float q = v.x*v.x + v.y*v.y + v.z*v.z + v.w*v.w;
#pragma unroll
    for (int o = 16; o; o >>= 1) {
        s += __shfl_xor_sync(0xffffffffu, s, o);
        q += __shfl_xor_sync(0xffffffffu, q, o);
    }
    if ((tid & 31) == 0) { sh_s[tid >> 5] = s; sh_q[tid >> 5] = q; }
    __syncthreads();
    if (tid < 32) {
        s = (tid < 8) ? sh_s[tid] : 0.f;
        q = (tid < 8) ? sh_q[tid] : 0.f;
#pragma unroll
        for (int o = 4; o; o >>= 1) {
            s += __shfl_xor_sync(0xffffffffu, s, o);
            q += __shfl_xor_sync(0xffffffffu, q, o);
        }
        if (tid == 0) { sh_s[0] = s; sh_q[0] = q; }
    }
    __syncthreads();
    s = sh_s[0]; q = sh_q[0];
    const float mean = s * (1.0f / DIM);
    const float var  = (q - (float)DIM * mean * mean) * (1.0f / (DIM - 1));
    const float inv  = 1.0f / (sqrtf(fmaxf(var, 0.f)) + 1e-6f);
    const float4 a = ((const float4*)alpha)[tid];
    const float4 b = ((const float4*)beta)[tid];
    const float ox = a.x * (v.x - mean) * inv + b.x;
    const float oy = a.y * (v.y - mean) * inv + b.y;
    const float oz = a.z * (v.z - mean) * inv + b.z;
    const float ow = a.w * (v.w - mean) * inv + b.w;
    *(uint2*)((uint16_t*)ln + row * DIM + 4 * tid) =
        make_uint2(pack_h2(ox, oy), pack_h2(oz, ow));
}

// ============ single-fp16 1-MMA GEMM, 3-stage pipeline (R13 proven) =========
// C[m,n] = sum_k A[m,k]*B[n,k] + bias (+relu, +resid), fp32 accumulate.
// 128 threads, 2x2 warps, 64x64 warp tiles, BM=BN=128, BK=64.
template<bool OHALF>
__global__ __launch_bounds__(128, 2) void gemm_h1(
    const __half* __restrict__ A, int lda,
    const __half* __restrict__ B, int ldb,
    float* __restrict__ Cf, __half* __restrict__ Ch, int ldc,
    int K,
    const float* __restrict__ bias,
    const float* __restrict__ resid, int ldr,
    int relu)
{
    constexpr int BK = 64;
    constexpr int TBYTES = 128 * 144;
    constexpr int SS = 2 * TBYTES;        // stage = A + B (36864)

    extern __shared__ char sm[];
    const uint32_t smBase = smem_u32(sm);

    const int tid = threadIdx.x, wid = tid >> 5, lane = tid & 31;
    const int wm = wid >> 1, wn = wid & 1;
    const int m0 = blockIdx.y * 128, n0 = blockIdx.x * 128;

    float acc[4][8][4];
#pragma unroll
    for (int i = 0; i < 4; i++)
#pragma unroll
        for (int j = 0; j < 8; j++)
#pragma unroll
            for (int r = 0; r < 4; r++) acc[i][j][r] = 0.f;

    auto issue = [&](int s, int t) {
        const uint32_t sA = smBase + s * SS;
        const uint32_t sB = sA + TBYTES;
#pragma unroll
        for (int i = 0; i < 8; i++) {
            const int idx = i * 128 + tid;
            const int c = idx & 7, row = idx >> 3;
            cp_async16(sA + row * 144 + c * 16,
                       A + (size_t)(m0 + row) * lda + t * BK + c * 8);
        }
#pragma unroll
        for (int i = 0; i < 8; i++) {
            const int idx = i * 128 + tid;
            const int c = idx & 7, row = idx >> 3;
            cp_async16(sB + row * 144 + c * 16,
                       B + (size_t)(n0 + row) * ldb + t * BK + c * 8);
        }
        CP_COMMIT();
    };

    auto compute = [&](int s) {
        const uint32_t aB = smBase + s * SS;
        const uint32_t bB = aB + TBYTES;
#pragma unroll
        for (int ks = 0; ks < 4; ks++) {
            uint32_t bf[8][2];
#pragma unroll
            for (int p = 0; p < 4; p++) {
                const uint32_t rb =
                    (uint32_t)((wn * 64 + p * 16 + ((lane >> 4) & 1) * 8 + (lane & 7)) * 144
                               + ks * 32 + ((lane >> 3) & 1) * 16);
                LDM4(bf[2*p][0], bf[2*p][1], bf[2*p+1][0], bf[2*p+1][1], bB + rb);
            }
#pragma unroll
            for (int mt = 0; mt < 4; mt++) {
                uint32_t af[4];
                const uint32_t ra =
                    (uint32_t)((wm * 64 + mt * 16 + (lane & 15)) * 144
                               + ks * 32 + (lane >> 4) * 16);
                LDM4(af[0], af[1], af[2], af[3], aB + ra);
#pragma unroll
                for (int nt = 0; nt < 8; nt++) MMAH16816(acc[mt][nt], af, bf[nt]);
            }
        }
    };

    const int T = K / BK;
    issue(0, 0);
    if (T > 1) issue(1, 1);
    CP_WAIT1();              // stage 0 ready (stage 1 may be in flight)
    __syncthreads();

    for (int t = 0; t < T; t++) {
        compute(t % 3);
        if (t + 1 < T) {
            if (t + 2 < T) {
                issue((t + 2) % 3, t + 2);   // buffer freed by compute(t-1)
                CP_WAIT1();                  // stage t+1 complete
            } else {
                CP_WAIT0();
            }
            __syncthreads();
        }
    }

#pragma unroll
    for (int mt = 0; mt < 4; mt++) {
#pragma unroll
        for (int nt = 0; nt < 8; nt++) {
            const int r0 = m0 + wm * 64 + mt * 16 + (lane >> 2);
            const int cc = n0 + wn * 64 + nt * 8 + (lane & 3) * 2;
#pragma unroll
            for (int h = 0; h < 2; h++) {
                const int m = r0 + h * 8;
                float vx = acc[mt][nt][2 * h];
                float vy = acc[mt][nt][2 * h + 1];
                if (bias)  { vx += bias[cc]; vy += bias[cc + 1]; }
                if (relu)  { vx = fmaxf(vx, 0.f); vy = fmaxf(vy, 0.f); }
                if (resid) {
                    const float2 rr = *(const float2*)(resid + (size_t)m * ldr + cc);
                    vx += rr.x; vy += rr.y;
                }
                if constexpr (OHALF) {
                    *(uint32_t*)(Ch + (size_t)m * ldc + cc) = pack_h2(vx, vy);
                } else {
                    *(float2*)(Cf + (size_t)m * ldc + cc) = make_float2(vx, vy);
                }
            }
        }
    }
}

// ============== fused flash attention, double-buffered KV ===================
#define FQ_B 9216       // 64 rows * 144B
#define FKV_B 36864     // K(18432) + V(18432) one stage
#define FSMEM (FQ_B + 2*FKV_B)   // 82944

__global__ __launch_bounds__(128, 2) void flash_attn(
    const __half* __restrict__ qkv, __half* __restrict__ o)
{
    extern __shared__ char sm[];
    const uint32_t smBase = smem_u32(sm);
    const int tid = threadIdx.x, lane = tid & 31, w = tid >> 5;
    const int b = blockIdx.y >> 4, h = blockIdx.y & 15;
    const size_t rowQ  = (size_t)b * SEQ + blockIdx.x * 64;
    const size_t rowKV = (size_t)b * SEQ;
    const int colh = h * DH;

    const uint32_t sQ = smBase;
    const uint32_t sKV0 = smBase + FQ_B;

    auto loadKV = [&](int kt, int s) {
        const uint32_t sK = sKV0 + s * FKV_B;
        const size_t base = (rowKV + kt * 128) * QKVN + colh;
#pragma unroll
        for (int i = 0; i < 16; i++) {
            const int idx = i * 128 + tid;
            const int kv = idx >> 10, c = idx & 7, row = (idx >> 3) & 127;
            const size_t off = base + (size_t)row * QKVN + c * 8 + (kv + 1) * DIM;
            cp_async16(sK + kv * 18432 + row * 144 + c * 16, qkv + off);
        }
        CP_COMMIT();
    };

#pragma unroll
    for (int i = 0; i < 4; i++) {
        const int idx = i * 128 + tid;
        const int c = idx & 7, row = idx >> 3;
        cp_async16(sQ + row * 144 + c * 16,
                   qkv + (rowQ + row) * QKVN + colh + c * 8);
    }
    loadKV(0, 0);          // commits Q + KV0 together
    loadKV(1, 1);
    CP_WAIT1();            // Q + KV0 ready
    __syncthreads();

    float oacc[8][4];
#pragma unroll
    for (int i = 0; i < 8; i++)
#pragma unroll
        for (int j = 0; j < 4; j++) oacc[i][j] = 0.f;
    float m0 = -INFINITY, m1 = -INFINITY, l0 = 0.f, l1 = 0.f;

    for (int kt = 0; kt < 8; kt++) {
        const int s = kt & 1;
        const uint32_t sK = sKV0 + s * FKV_B;
        const uint32_t sV = sK + 18432;

        float sfr[16][4];
#pragma unroll
        for (int i = 0; i < 16; i++)
#pragma unroll
            for (int j = 0; j < 4; j++) sfr[i][j] = 0.f;
#pragma unroll
        for (int ks = 0; ks < 4; ks++) {
            uint32_t qa[4];
            const uint32_t ra = sQ + (w * 16 + (lane & 15)) * 144
                              + ks * 32 + (lane >> 4) * 16;
            LDM4(qa[0], qa[1], qa[2], qa[3], ra);
#pragma unroll
            for (int p = 0; p < 8; p++) {
                uint32_t kb[4];
                const uint32_t rb = sK + (p * 16 + ((lane >> 4) & 1) * 8 + (lane & 7)) * 144
                                  + ks * 32 + ((lane >> 3) & 1) * 16;
                LDM4(kb[0], kb[1], kb[2], kb[3], rb);
                MMAH16816(sfr[2*p],   qa, (&kb[0]));
                MMAH16816(sfr[2*p+1], qa, (&kb[2]));
            }
        }
        float mx0 = -INFINITY, mx1 = -INFINITY;
#pragma unroll
        for (int nt = 0; nt < 16; nt++) {
            mx0 = fmaxf(mx0, fmaxf(sfr[nt][0], sfr[nt][1]));
            mx1 = fmaxf(mx1, fmaxf(sfr[nt][2], sfr[nt][3]));
        }
        mx0 = fmaxf(mx0, __shfl_xor_sync(0xffffffffu, mx0, 1));
        mx0 = fmaxf(mx0, __shfl_xor_sync(0xffffffffu, mx0, 2));
        mx1 = fmaxf(mx1, __shfl_xor_sync(0xffffffffu, mx1, 1));
        mx1 = fmaxf(mx1, __shfl_xor_sync(0xffffffffu, mx1, 2));
        const float mn0 = fmaxf(m0, 0.125f * mx0);
        const float mn1 = fmaxf(m1, 0.125f * mx1);
        const float f0 = __expf(m0 - mn0);
        const float f1 = __expf(m1 - mn1);
        float rs0 = 0.f, rs1 = 0.f;
#pragma unroll
        for (int nt = 0; nt < 16; nt++) {
            const float p0 = __expf(fmaf(sfr[nt][0], 0.125f, -mn0));
            const float p1 = __expf(fmaf(sfr[nt][1], 0.125f, -mn0));
            const float p2 = __expf(fmaf(sfr[nt][2], 0.125f, -mn1));
            const float p3 = __expf(fmaf(sfr[nt][3], 0.125f, -mn1));
            rs0 += p0 + p1; rs1 += p2 + p3;
            sfr[nt][0] = p0; sfr[nt][1] = p1; sfr[nt][2] = p2; sfr[nt][3] = p3;
        }
        rs0 += __shfl_xor_sync(0xffffffffu, rs0, 1);
        rs0 += __shfl_xor_sync(0xffffffffu, rs0, 2);
        rs1 += __shfl_xor_sync(0xffffffffu, rs1, 1);
        rs1 += __shfl_xor_sync(0xffffffffu, rs1, 2);
        l0 = l0 * f0 + rs0; l1 = l1 * f1 + rs1;
        m0 = mn0; m1 = mn1;
#pragma unroll
        for (int dt = 0; dt < 8; dt++) {
            oacc[dt][0] *= f0; oacc[dt][1] *= f0;
            oacc[dt][2] *= f1; oacc[dt][3] *= f1;
        }
#pragma unroll
        for (int ks = 0; ks < 8; ks++) {
            uint32_t pa[4];
            pa[0] = pack_h2(sfr[2 * ks][0],     sfr[2 * ks][1]);
            pa[1] = pack_h2(sfr[2 * ks][2],     sfr[2 * ks][3]);
            pa[2] = pack_h2(sfr[2 * ks + 1][0], sfr[2 * ks + 1][1]);
            pa[3] = pack_h2(sfr[2 * ks + 1][2], sfr[2 * ks + 1][3]);
#pragma unroll
            for (int dt = 0; dt < 8; dt++) {
                uint32_t vb[2];
                const uint32_t rv = sV + (ks * 16 + (lane & 15)) * 144 + dt * 16;
                LDM2T(vb[0], vb[1], rv);
                MMAH16816(oacc[dt], pa, vb);
            }
        }
        if (kt + 1 < 8) {
            __syncthreads();
            if (kt + 2 < 8) {
                loadKV(kt + 2, s);
                CP_WAIT1();
            } else {
                CP_WAIT0();
            }
            __syncthreads();
        }
    }

    const float i0 = 1.f / l0, i1 = 1.f / l1;
    const int r = w * 16 + (lane >> 2);
    const int cc = (lane & 3) * 2;
#pragma unroll
    for (int dt = 0; dt < 8; dt++) {
        const size_t o0 = (rowQ + r) * DIM + colh + dt * 8 + cc;
        *(uint32_t*)(o + o0) = pack_h2(oacc[dt][0] * i0, oacc[dt][1] * i0);
        const size_t o1 = o0 + 8 * DIM;
        *(uint32_t*)(o + o1) = pack_h2(oacc[dt][2] * i1, oacc[dt][3] * i1);
    }
}

// ---------------- LayerNorm -> single fp16 plane (LN2) ---------------------
__global__ __launch_bounds__(256) void ln_kernel(const float* __restrict__ x,
                                                 __half* __restrict__ y,
                                                 const float* __restrict__ alpha,
                                                 const float* __restrict__ beta) {
    __shared__ float sh_s[8], sh_q[8];
    const size_t row = blockIdx.x;
    const float4* xr = (const float4*)(x + row * DIM);
    const int tid = threadIdx.x;
    float4 v = xr[tid];
    float s = v.x + v.y + v.z + v.w;
    float q = v.x*v.x + v.y*v.y + v.z*v.z + v.w*v.w;
#pragma unroll
    for (int o = 16; o; o >>= 1) {
        s += __shfl_xor_sync(0xffffffffu, s, o);
        q += __shfl_xor_sync(0xffffffffu, q, o);
    }
    if ((tid & 31) == 0) { sh_s[tid >> 5] = s; sh_q[tid >> 5] = q; }
    __syncthreads();
    if (tid < 32) {
        s = (tid < 8) ? sh_s[tid] : 0.f;
        q = (tid < 8) ? sh_q[tid] : 0.f;
#pragma unroll
        for (int o = 4; o; o >>= 1) {
            s += __shfl_xor_sync(0xffffffffu, s, o);
            q += __shfl_xor_sync(0xffffffffu, q, o);
        }
        if (tid == 0) { sh_s[0] = s; sh_q[0] = q; }
    }
    __syncthreads();
    s = sh_s[0]; q = sh_q[0];
    const float mean = s * (1.0f / DIM);
    const float var  = (q - (float)DIM * mean * mean) * (1.0f / (DIM - 1));
    const float inv  = 1.0f / (sqrtf(fmaxf(var, 0.f)) + 1e-6f);
    const float4 a = ((const float4*)alpha)[tid];
    const float4 b = ((const float4*)beta)[tid];
    const float ox = a.x * (v.x - mean) * inv + b.x;
    const float oy = a.y * (v.y - mean) * inv + b.y;
    const float oz = a.z * (v.z - mean) * inv + b.z;
    const float ow = a.w * (v.w - mean) * inv + b.w;
    *(uint2*)((uint16_t*)y + row * DIM + 4 * tid) =
        make_uint2(pack_h2(ox, oy), pack_h2(oz, ow));
}

// ---------------- launch ----------------------------------------------------
template<typename T>
static T* symaddr(const void* s) {
    void* p = nullptr;
    cudaGetSymbolAddress(&p, s);
    return (T*)p;
}

#define SMEM_H1 (3 * (2 * 128 * 144))   // 110592

extern "C" void kernel_launch(void* const* d_in, const int* in_sizes, int n_in,
                              void* d_out, int out_size) {
    (void)in_sizes; (void)n_in; (void)out_size;
    const float* x     = (const float*)d_in[0];
    const float* wq    = (const float*)d_in[2];
    const float* bq    = (const float*)d_in[3];
    const float* wk    = (const float*)d_in[4];
    const float* bk    = (const float*)d_in[5];
    const float* wv    = (const float*)d_in[6];
    const float* bv    = (const float*)d_in[7];
    const float* wo    = (const float*)d_in[8];
    const float* bo    = (const float*)d_in[9];
    const float* w1    = (const float*)d_in[10];
    const float* b1    = (const float*)d_in[11];
    const float* w2    = (const float*)d_in[12];
    const float* b2    = (const float*)d_in[13];
    const float* alpha = (const float*)d_in[14];
    const float* beta  = (const float*)d_in[15];
    float* out = (float*)d_out;

    cudaFuncSetAttribute(gemm_h1<true>,
                         cudaFuncAttributeMaxDynamicSharedMemorySize, SMEM_H1);
    cudaFuncSetAttribute(gemm_h1<false>,
                         cudaFuncAttributeMaxDynamicSharedMemorySize, SMEM_H1);
    cudaFuncSetAttribute(flash_attn,
                         cudaFuncAttributeMaxDynamicSharedMemorySize, FSMEM);

    __half* ln   = symaddr<__half>(g_ln);
    __half* qkv  = symaddr<__half>(g_qkv);
    float*  x1   = symaddr<float>(g_x1);
    __half* w16  = symaddr<__half>(g_w16);
    __half* hid  = symaddr<__half>(g_hid);
    float*  b3   = symaddr<float>(g_b3);

    // 0) fused prep: all weight conversions + bias concat + LN1
    prep_kernel<<<PREP_BLOCKS, 256>>>(wq, wk, wv, wo, w1, w2,
                                      bq, bk, bv, x, alpha, beta,
                                      w16, b3, ln);

    // 1) fused QKV projection [8192, 3072]
    dim3 gqkv(QKVN / 128, MROWS / 128, 1);
    gemm_h1<true><<<gqkv, 128, SMEM_H1>>>(
        ln, DIM, w16 + HOFF_QKV, DIM,
        nullptr, qkv, QKVN, DIM, b3, nullptr, 0, 0);

    // 2) fused attention -> fp16 plane (reuse ln buffer)
    dim3 gfa(SEQ / 64, BATCH * HEADS, 1);
    flash_attn<<<gfa, 128, FSMEM>>>(qkv, ln);

    // 3) O projection + residual x -> x1 (fp32)
    dim3 gw(DIM / 128, MROWS / 128, 1);
    gemm_h1<false><<<gw, 128, SMEM_H1>>>(
        ln, DIM, w16 + HOFF_O, DIM,
        x1, nullptr, DIM, DIM, bo, x, DIM, 0);

    // 4) LN2
    ln_kernel<<<MROWS, 256>>>(x1, ln, alpha, beta);

    // 5) FFN1 (+ReLU) -> fp16 hidden
    dim3 gf1(HFF / 128, MROWS / 128, 1);
    gemm_h1<true><<<gf1, 128, SMEM_H1>>>(
        ln, DIM, w16 + HOFF_1, DIM,
        nullptr, hid, HFF, DIM, b1, nullptr, 0, 1);

    // 6) FFN2 + residual x1 -> out (fp32)
    dim3 gf2(DIM / 128, MROWS / 128, 1);
    gemm_h1<false><<<gf2, 128, SMEM_H1>>>(
        hid, HFF, w16 + HOFF_2, HFF,
        out, nullptr, DIM, HFF, b2, x1, DIM, 0);
}